// round 12
// baseline (speedup 1.0000x reference)
#include <cuda_runtime.h>
#include <cuda_bf16.h>
#include <cstdint>

#define N_ATOMS 40000
#define N_PAIRS 640000
#define DD 128
#define RR 20

// Scratch (allocation-free rule: static device globals)
__device__ float g_h[N_ATOMS * DD];    // 20.48 MB
__device__ float g_agg[N_ATOMS * DD];  // 20.48 MB

// Packed fp32x2 FMA (validated: GEMM at 31.9 TF/s with fma-pipe 42% active)
#define FFMA2(acc, a, b) \
    asm("fma.rn.f32x2 %0, %1, %2, %0;" : "+l"(acc) : "l"(a), "l"(b))

__device__ __forceinline__ unsigned long long pack2(float x, float y) {
    unsigned long long d;
    asm("mov.b64 %0, {%1,%2};" : "=l"(d) : "f"(x), "f"(y));
    return d;
}
__device__ __forceinline__ void unpack2(unsigned long long d, float& x, float& y) {
    asm("mov.b64 {%0,%1}, %2;" : "=f"(x), "=f"(y) : "l"(d));
}
// NOTE: no "memory" clobber — nothing reads agg inside this kernel, and we
// want subsequent gathers to hoist above the RED for MLP.
__device__ __forceinline__ void red_add_v4(float* addr, float a, float b,
                                           float c, float d) {
    asm volatile("red.global.add.v4.f32 [%0], {%1, %2, %3, %4};"
                 :: "l"(addr), "f"(a), "f"(b), "f"(c), "f"(d));
}

// Branch-free shifted softplus: max(x,0) + log1p(e^-|x|) - ln2
__device__ __forceinline__ float sspf(float x) {
    float e = __expf(-fabsf(x));
    return fmaxf(x, 0.f) + (__logf(1.f + e) - 0.69314718055994531f);
}

// -----------------------------------------------------------------------------
// Tiled SGEMM, double-buffered smem: ONE barrier per k-tile (the measured wall
// was the 2-barrier structure). Register prefetch of next tile kept.
// ZERO variant also zeroes this block's slice of zbuf.
// -----------------------------------------------------------------------------
template <bool SSP, bool ZERO>
__global__ __launch_bounds__(256) void gemm_atoms(
    const float* __restrict__ A, const float* __restrict__ W,
    const float* __restrict__ bias, float* __restrict__ out,
    float* __restrict__ zbuf)
{
    __shared__ float As[2][16][68];
    __shared__ float Bs[2][16][132];

    const int tid  = threadIdx.x;
    const int tcol = tid & 31;
    const int trow = tid >> 5;
    const int a0   = blockIdx.x * 64;

    const int ar = tid >> 2, akg = (tid & 3) << 2;
    const int wc0 = tid >> 2,         wk0g = (tid & 3) << 2;
    const int wc1 = (tid + 256) >> 2, wk1g = ((tid + 256) & 3) << 2;

    if (ZERO) {
        float4* z = (float4*)(zbuf + (size_t)a0 * DD);
        const float4 z4 = make_float4(0.f, 0.f, 0.f, 0.f);
#pragma unroll
        for (int i = 0; i < 8; i++) z[tid + i * 256] = z4;
    }

    unsigned long long accp[4][4];
#pragma unroll
    for (int p = 0; p < 4; p++)
#pragma unroll
        for (int j = 0; j < 4; j++) accp[p][j] = 0ull;

    // Prologue: tile 0 into registers
    float4 va  = *(const float4*)&A[(size_t)(a0 + ar) * 128 + akg];
    float4 vw0 = *(const float4*)&W[(size_t)wc0 * 128 + wk0g];
    float4 vw1 = *(const float4*)&W[(size_t)wc1 * 128 + wk1g];

#pragma unroll
    for (int kt8 = 0; kt8 < 8; kt8++) {
        const int b = kt8 & 1;
        As[b][akg + 0][ar] = va.x; As[b][akg + 1][ar] = va.y;
        As[b][akg + 2][ar] = va.z; As[b][akg + 3][ar] = va.w;
        Bs[b][wk0g + 0][wc0] = vw0.x; Bs[b][wk0g + 1][wc0] = vw0.y;
        Bs[b][wk0g + 2][wc0] = vw0.z; Bs[b][wk0g + 3][wc0] = vw0.w;
        Bs[b][wk1g + 0][wc1] = vw1.x; Bs[b][wk1g + 1][wc1] = vw1.y;
        Bs[b][wk1g + 2][wc1] = vw1.z; Bs[b][wk1g + 3][wc1] = vw1.w;
        __syncthreads();   // single barrier per tile (double buffer)

        if (kt8 < 7) {
            const int kt = (kt8 + 1) * 16;
            va  = *(const float4*)&A[(size_t)(a0 + ar) * 128 + kt + akg];
            vw0 = *(const float4*)&W[(size_t)wc0 * 128 + kt + wk0g];
            vw1 = *(const float4*)&W[(size_t)wc1 * 128 + kt + wk1g];
        }

#pragma unroll
        for (int k = 0; k < 16; k++) {
            float4 bv = *(const float4*)&Bs[b][k][tcol * 4];
            unsigned long long bb[4];
            bb[0] = pack2(bv.x, bv.x); bb[1] = pack2(bv.y, bv.y);
            bb[2] = pack2(bv.z, bv.z); bb[3] = pack2(bv.w, bv.w);
            const unsigned long long* ap =
                (const unsigned long long*)&As[b][k][trow * 8];
            unsigned long long a[4];
            a[0] = ap[0]; a[1] = ap[1]; a[2] = ap[2]; a[3] = ap[3];
#pragma unroll
            for (int p = 0; p < 4; p++)
#pragma unroll
                for (int j = 0; j < 4; j++) FFMA2(accp[p][j], a[p], bb[j]);
        }
    }

    float4 bia = *(const float4*)&bias[tcol * 4];
    float bb[4] = {bia.x, bia.y, bia.z, bia.w};
#pragma unroll
    for (int p = 0; p < 4; p++) {
        float lo[4], hi[4];
#pragma unroll
        for (int j = 0; j < 4; j++) {
            unpack2(accp[p][j], lo[j], hi[j]);
            lo[j] += bb[j]; hi[j] += bb[j];
            if (SSP) { lo[j] = sspf(lo[j]); hi[j] = sspf(hi[j]); }
        }
        size_t r0 = (size_t)(a0 + trow * 8 + 2 * p) * 128 + tcol * 4;
        *(float4*)&out[r0]       = make_float4(lo[0], lo[1], lo[2], lo[3]);
        *(float4*)&out[r0 + 128] = make_float4(hi[0], hi[1], hi[2], hi[3]);
    }
}

// -----------------------------------------------------------------------------
// Pair kernel v4 — "transpose trick", two phases per 32-pair chunk:
//  Phase A (lane = pair): f in 10 u64 regs; sweep this warp's 32 channels with
//    warp-uniform broadcast LDS.128 of packed W_f; S=ssp(dot+bias)*rc -> sS.
//  Phase B (lane = channel): wv=LDS.128 from sS, gather h LDG.128, RED.128.
// Weights live in SMEM (10KB), not registers -> ~75 regs -> ~2x occupancy.
// -----------------------------------------------------------------------------
#define PCHUNK 32

__global__ __launch_bounds__(128) void pair_kernel(
    const float* __restrict__ f_ij, const int* __restrict__ idx_i,
    const int* __restrict__ idx_j, const float* __restrict__ rcut,
    const float* __restrict__ W_f, const float* __restrict__ b_f,
    const float* __restrict__ h, float* __restrict__ agg)
{
    __shared__ __align__(16) unsigned long long sWp[DD][10];  // 10KB, k-packed
    __shared__ float sBias[DD];
    __shared__ __align__(16) float sS[PCHUNK][132];           // 16.9KB padded
    __shared__ int sI[PCHUNK];
    __shared__ int sJ[PCHUNK];

    const int tid  = threadIdx.x;
    const int lane = tid & 31;
    const int warp = tid >> 5;       // 0..3

    // Stage packed weights + bias once (thread t = channel t)
    {
        const float2* row = (const float2*)&W_f[(size_t)tid * RR];
#pragma unroll
        for (int k = 0; k < 10; k++) {
            float2 v = __ldg(&row[k]);
            sWp[tid][k] = pack2(v.x, v.y);
        }
        sBias[tid] = __ldg(&b_f[tid]);
    }
    __syncthreads();

    const int nchunks = N_PAIRS / PCHUNK;   // 20000
    for (int ch = blockIdx.x; ch < nchunks; ch += gridDim.x) {
        const int base = ch * PCHUNK;
        const int p    = base + lane;       // this lane's pair (all 4 warps same)

        // f for my pair: 5 x LDG.128 (warps share lines -> L1 hits)
        const float4* fp = (const float4*)&f_ij[(size_t)p * RR];
        float4 v0 = fp[0], v1 = fp[1], v2 = fp[2], v3 = fp[3], v4 = fp[4];
        unsigned long long f[10];
        f[0] = pack2(v0.x, v0.y); f[1] = pack2(v0.z, v0.w);
        f[2] = pack2(v1.x, v1.y); f[3] = pack2(v1.z, v1.w);
        f[4] = pack2(v2.x, v2.y); f[5] = pack2(v2.z, v2.w);
        f[6] = pack2(v3.x, v3.y); f[7] = pack2(v3.z, v3.w);
        f[8] = pack2(v4.x, v4.y); f[9] = pack2(v4.z, v4.w);
        const float rc = __ldg(&rcut[p]);
        if (warp == 0) {
            sI[lane] = idx_i[p];
            sJ[lane] = idx_j[p];
        }

        // ---- Phase A: my warp's 32 channels for all 32 pairs ----
        const int cbeg = warp << 5;
#pragma unroll 2
        for (int cc = 0; cc < 32; cc++) {
            const int c = cbeg + cc;
            const ulonglong2* wr = (const ulonglong2*)&sWp[c][0]; // uniform bcast
            ulonglong2 wa = wr[0], wb = wr[1], wc2 = wr[2], wd = wr[3], we = wr[4];
            unsigned long long acc = 0ull;
            FFMA2(acc, f[0], wa.x); FFMA2(acc, f[1], wa.y);
            FFMA2(acc, f[2], wb.x); FFMA2(acc, f[3], wb.y);
            FFMA2(acc, f[4], wc2.x); FFMA2(acc, f[5], wc2.y);
            FFMA2(acc, f[6], wd.x); FFMA2(acc, f[7], wd.y);
            FFMA2(acc, f[8], we.x); FFMA2(acc, f[9], we.y);
            float lo, hi;
            unpack2(acc, lo, hi);
            const float s = lo + hi + sBias[c];
            sS[lane][c] = sspf(s) * rc;
        }
        __syncthreads();

        // ---- Phase B: my warp's 8 pairs, all 128 channels (lane = ch quad) ----
        const int c0 = lane << 2;
#pragma unroll
        for (int qi = 0; qi < 8; qi++) {
            const int q  = (warp << 3) + qi;
            const int jj = sJ[q];
            const int ii = sI[q];
            float4 wv = *(const float4*)&sS[q][c0];
            float4 hv = *(const float4*)&h[(size_t)jj * DD + c0];
            red_add_v4(&agg[(size_t)ii * DD + c0],
                       hv.x * wv.x, hv.y * wv.y, hv.z * wv.z, hv.w * wv.w);
        }
        __syncthreads();   // sS free before next chunk's phase A
    }
}

extern "C" void kernel_launch(void* const* d_in, const int* in_sizes, int n_in,
                              void* d_out, int out_size)
{
    const float* x     = (const float*)d_in[0];
    const float* f_ij  = (const float*)d_in[1];
    const int*   idx_i = (const int*)d_in[2];
    const int*   idx_j = (const int*)d_in[3];
    const float* rcut  = (const float*)d_in[4];
    const float* W_in  = (const float*)d_in[5];
    const float* b_in  = (const float*)d_in[6];
    const float* W_f   = (const float*)d_in[7];
    const float* b_f   = (const float*)d_in[8];
    const float* W_out = (const float*)d_in[9];
    const float* b_out = (const float*)d_in[10];
    float* out = (float*)d_out;

    float* hptr = nullptr;
    float* aptr = nullptr;
    cudaGetSymbolAddress((void**)&hptr, g_h);
    cudaGetSymbolAddress((void**)&aptr, g_agg);

    // GEMM #1 also zeroes agg (absorbs the standalone zero kernel)
    gemm_atoms<false, true><<<N_ATOMS / 64, 256>>>(x, W_in, b_in, hptr, aptr);
    pair_kernel<<<1184, 128>>>(f_ij, idx_i, idx_j, rcut, W_f, b_f, hptr, aptr);
    gemm_atoms<true, false><<<N_ATOMS / 64, 256>>>(aptr, W_out, b_out, out, aptr);
}

// round 15
// speedup vs baseline: 1.1024x; 1.1024x over previous
#include <cuda_runtime.h>
#include <cuda_bf16.h>
#include <cstdint>

#define N_ATOMS 40000
#define N_PAIRS 640000
#define DD 128
#define RR 20

// Scratch (allocation-free rule: static device globals)
__device__ float g_h[N_ATOMS * DD];    // 20.48 MB
__device__ float g_agg[N_ATOMS * DD];  // 20.48 MB

// Packed fp32x2 FMA (validated: 31.9 TF/s with fma-pipe 42% active)
#define FFMA2(acc, a, b) \
    asm("fma.rn.f32x2 %0, %1, %2, %0;" : "+l"(acc) : "l"(a), "l"(b))

__device__ __forceinline__ unsigned long long pack2(float x, float y) {
    unsigned long long d;
    asm("mov.b64 %0, {%1,%2};" : "=l"(d) : "f"(x), "f"(y));
    return d;
}
__device__ __forceinline__ void unpack2(unsigned long long d, float& x, float& y) {
    asm("mov.b64 {%0,%1}, %2;" : "=f"(x), "=f"(y) : "l"(d));
}
__device__ __forceinline__ void red_add_v4(float* addr, float a, float b,
                                           float c, float d) {
    asm volatile("red.global.add.v4.f32 [%0], {%1, %2, %3, %4};"
                 :: "l"(addr), "f"(a), "f"(b), "f"(c), "f"(d));
}
__device__ __forceinline__ uint32_t smem_u32(const void* p) {
    uint32_t a;
    asm("{ .reg .u64 t; cvta.to.shared.u64 t, %1; cvt.u32.u64 %0, t; }"
        : "=r"(a) : "l"(p));
    return a;
}
#define CP_ASYNC16(saddr, gptr) \
    asm volatile("cp.async.ca.shared.global [%0], [%1], 16;" \
                 :: "r"(saddr), "l"(gptr) : "memory")
#define CP_COMMIT() asm volatile("cp.async.commit_group;" ::: "memory")
#define CP_WAIT0()  asm volatile("cp.async.wait_group 0;" ::: "memory")

// Branch-free shifted softplus: max(x,0) + log1p(e^-|x|) - ln2
__device__ __forceinline__ float sspf(float x) {
    float e = __expf(-fabsf(x));
    return fmaxf(x, 0.f) + (__logf(1.f + e) - 0.69314718055994531f);
}

// -----------------------------------------------------------------------------
// SGEMM v2: BM=128, BN=128, BK=8, 256 threads (16x16), 8x8 microtile.
// Fixes the measured smem-crossbar bound (L1=61.9% > fma=42%): per warp per k
// ~6 wavefronts now feed 32 FFMA2 (was 6 wf : 16 FFMA2) -> fma-pipe bound.
// Double-buffered smem, one barrier per k-tile, register prefetch.
// M=40000 handled by row-clamped loads + guarded stores (grid=313).
// ZERO variant also zeroes this block's slice of zbuf.
// -----------------------------------------------------------------------------
template <bool SSP, bool ZERO>
__global__ __launch_bounds__(256) void gemm_atoms(
    const float* __restrict__ A, const float* __restrict__ W,
    const float* __restrict__ bias, float* __restrict__ out,
    float* __restrict__ zbuf)
{
    __shared__ float As[2][8][132];
    __shared__ float Bs[2][8][132];

    const int tid = threadIdx.x;
    const int rt  = tid >> 4;        // row tile 0..15 -> rows rt*8..rt*8+7
    const int ct  = tid & 15;        // col tile 0..15 -> cols ct*8..ct*8+7
    const int a0  = blockIdx.x * 128;

    // Staging coords: thread covers (row srow, k skg..skg+3)
    const int srow = tid >> 1;
    const int skg  = (tid & 1) << 2;
    int arow = a0 + srow;
    if (arow >= N_ATOMS) arow = N_ATOMS - 1;   // clamp (stores are guarded)

    if (ZERO) {
#pragma unroll
        for (int i = 0; i < 16; i++) {
            int idx = tid + i * 256;            // 0..4095
            int row = idx >> 5, c4 = idx & 31;
            int grow = a0 + row;
            if (grow < N_ATOMS)
                ((float4*)&zbuf[(size_t)grow * DD])[c4] =
                    make_float4(0.f, 0.f, 0.f, 0.f);
        }
    }

    unsigned long long acc[4][8];   // [row-pair][col]
#pragma unroll
    for (int p = 0; p < 4; p++)
#pragma unroll
        for (int j = 0; j < 8; j++) acc[p][j] = 0ull;

    // Prologue: k-tile 0 into registers
    float4 va = *(const float4*)&A[(size_t)arow * 128 + skg];
    float4 vw = *(const float4*)&W[(size_t)srow * 128 + skg];

#pragma unroll
    for (int kt8 = 0; kt8 < 16; kt8++) {
        const int b = kt8 & 1;
        As[b][skg + 0][srow] = va.x; As[b][skg + 1][srow] = va.y;
        As[b][skg + 2][srow] = va.z; As[b][skg + 3][srow] = va.w;
        Bs[b][skg + 0][srow] = vw.x; Bs[b][skg + 1][srow] = vw.y;
        Bs[b][skg + 2][srow] = vw.z; Bs[b][skg + 3][srow] = vw.w;
        __syncthreads();   // single barrier per tile (double buffer)

        if (kt8 < 15) {
            const int kt = (kt8 + 1) * 8;
            va = *(const float4*)&A[(size_t)arow * 128 + kt + skg];
            vw = *(const float4*)&W[(size_t)srow * 128 + kt + skg];
        }

#pragma unroll
        for (int k = 0; k < 8; k++) {
            // A: 8 rows as 4 u64 (2 x LDS.128, warp-broadcast: rt is 2-valued/warp)
            const ulonglong2* ap = (const ulonglong2*)&As[b][k][rt * 8];
            ulonglong2 A01 = ap[0], A23 = ap[1];
            unsigned long long a[4] = {A01.x, A01.y, A23.x, A23.y};
            // B: 8 cols as 2 float4 (16 distinct 16B addrs/warp -> 2wf each)
            float4 b0 = *(const float4*)&Bs[b][k][ct * 8];
            float4 b1 = *(const float4*)&Bs[b][k][ct * 8 + 4];
            unsigned long long bb[8];
            bb[0] = pack2(b0.x, b0.x); bb[1] = pack2(b0.y, b0.y);
            bb[2] = pack2(b0.z, b0.z); bb[3] = pack2(b0.w, b0.w);
            bb[4] = pack2(b1.x, b1.x); bb[5] = pack2(b1.y, b1.y);
            bb[6] = pack2(b1.z, b1.z); bb[7] = pack2(b1.w, b1.w);
#pragma unroll
            for (int p = 0; p < 4; p++)
#pragma unroll
                for (int j = 0; j < 8; j++) FFMA2(acc[p][j], a[p], bb[j]);
        }
    }

    float4 bi0 = *(const float4*)&bias[ct * 8];
    float4 bi1 = *(const float4*)&bias[ct * 8 + 4];
    const float bv[8] = {bi0.x, bi0.y, bi0.z, bi0.w, bi1.x, bi1.y, bi1.z, bi1.w};
#pragma unroll
    for (int p = 0; p < 4; p++) {
        float lo[8], hi[8];
#pragma unroll
        for (int j = 0; j < 8; j++) {
            unpack2(acc[p][j], lo[j], hi[j]);
            lo[j] += bv[j]; hi[j] += bv[j];
            if (SSP) { lo[j] = sspf(lo[j]); hi[j] = sspf(hi[j]); }
        }
        const int grow = a0 + rt * 8 + 2 * p;
        if (grow < N_ATOMS) {
            float* o = &out[(size_t)grow * 128 + ct * 8];
            *(float4*)o       = make_float4(lo[0], lo[1], lo[2], lo[3]);
            *(float4*)(o + 4) = make_float4(lo[4], lo[5], lo[6], lo[7]);
        }
        if (grow + 1 < N_ATOMS) {
            float* o = &out[(size_t)(grow + 1) * 128 + ct * 8];
            *(float4*)o       = make_float4(hi[0], hi[1], hi[2], hi[3]);
            *(float4*)(o + 4) = make_float4(hi[4], hi[5], hi[6], hi[7]);
        }
    }
}

// -----------------------------------------------------------------------------
// Pair kernel (R11 verbatim — measured best, ~127us): warp-per-pair, 4
// ch/thread, q-level software pipeline (gather for q+4 prefetched), cp.async
// double-buffered chunk staging, CHUNK=32 pairs.
// -----------------------------------------------------------------------------
#define CHUNK 32

__global__ __launch_bounds__(128) void pair_kernel(
    const float* __restrict__ f_ij, const int* __restrict__ idx_i,
    const int* __restrict__ idx_j, const float* __restrict__ rcut,
    const float* __restrict__ W_f, const float* __restrict__ b_f,
    const float* __restrict__ h, float* __restrict__ agg)
{
    __shared__ __align__(16) float sF[2][CHUNK * RR];
    __shared__ __align__(16) float sR[2][CHUNK];
    __shared__ __align__(16) int   sI[2][CHUNK];
    __shared__ __align__(16) int   sJ[2][CHUNK];

    const int tid  = threadIdx.x;
    const int lane = tid & 31;
    const int warp = tid >> 5;
    const int c0   = lane * 4;

    unsigned long long wk[4][10];
    float bf[4];
#pragma unroll
    for (int c = 0; c < 4; c++) {
        const float2* row = (const float2*)&W_f[(size_t)(c0 + c) * RR];
#pragma unroll
        for (int k = 0; k < 10; k++) {
            float2 v = __ldg(&row[k]);
            wk[c][k] = pack2(v.x, v.y);
        }
        bf[c] = __ldg(&b_f[c0 + c]);
    }

    const int nchunks = N_PAIRS / CHUNK;

    auto stage = [&](int ch, int b) {
        const int base = ch * CHUNK;
        const char* fsrc = (const char*)&f_ij[(size_t)base * RR];
        uint32_t sf = smem_u32(&sF[b][0]);
        CP_ASYNC16(sf + tid * 16, fsrc + tid * 16);
        if (tid < 32) {
            CP_ASYNC16(sf + (tid + 128) * 16, fsrc + (tid + 128) * 16);
        } else if (tid < 40) {
            int t = tid - 32;
            CP_ASYNC16(smem_u32(&sR[b][0]) + t * 16,
                       (const char*)&rcut[base] + t * 16);
        } else if (tid < 48) {
            int t = tid - 40;
            CP_ASYNC16(smem_u32(&sI[b][0]) + t * 16,
                       (const char*)&idx_i[base] + t * 16);
        } else if (tid < 56) {
            int t = tid - 48;
            CP_ASYNC16(smem_u32(&sJ[b][0]) + t * 16,
                       (const char*)&idx_j[base] + t * 16);
        }
        CP_COMMIT();
    };

    int ch = blockIdx.x;
    if (ch < nchunks) stage(ch, 0);

    int it = 0;
    for (; ch < nchunks; ch += gridDim.x, ++it) {
        const int buf = it & 1;
        CP_WAIT0();
        __syncthreads();
        const int nch = ch + gridDim.x;
        if (nch < nchunks) stage(nch, buf ^ 1);

        int   q  = warp;
        int   ii = sI[buf][q];
        float rc = sR[buf][q];
        float4 hv = *(const float4*)&h[(size_t)sJ[buf][q] * DD + c0];

#pragma unroll
        for (int qi = 0; qi < 8; qi++) {
            int ii2; float rc2; float4 hv2;
            if (qi < 7) {
                const int qn = q + 4;
                ii2 = sI[buf][qn];
                rc2 = sR[buf][qn];
                hv2 = *(const float4*)&h[(size_t)sJ[buf][qn] * DD + c0];
            }

            const float4* fq = (const float4*)&sF[buf][q * RR];
            float4 v0 = fq[0], v1 = fq[1], v2 = fq[2], v3 = fq[3], v4 = fq[4];
            unsigned long long f[10];
            f[0] = pack2(v0.x, v0.y); f[1] = pack2(v0.z, v0.w);
            f[2] = pack2(v1.x, v1.y); f[3] = pack2(v1.z, v1.w);
            f[4] = pack2(v2.x, v2.y); f[5] = pack2(v2.z, v2.w);
            f[6] = pack2(v3.x, v3.y); f[7] = pack2(v3.z, v3.w);
            f[8] = pack2(v4.x, v4.y); f[9] = pack2(v4.z, v4.w);

            unsigned long long a0 = pack2(bf[0], 0.f);
            unsigned long long a1 = pack2(bf[1], 0.f);
            unsigned long long a2 = pack2(bf[2], 0.f);
            unsigned long long a3 = pack2(bf[3], 0.f);
#pragma unroll
            for (int k = 0; k < 10; k++) {
                FFMA2(a0, f[k], wk[0][k]);
                FFMA2(a1, f[k], wk[1][k]);
                FFMA2(a2, f[k], wk[2][k]);
                FFMA2(a3, f[k], wk[3][k]);
            }
            float l0, h0, l1, h1, l2, h2, l3, h3;
            unpack2(a0, l0, h0); unpack2(a1, l1, h1);
            unpack2(a2, l2, h2); unpack2(a3, l3, h3);
            const float w0 = sspf(l0 + h0) * rc;
            const float w1 = sspf(l1 + h1) * rc;
            const float w2 = sspf(l2 + h2) * rc;
            const float w3 = sspf(l3 + h3) * rc;

            red_add_v4(&agg[(size_t)ii * DD + c0],
                       hv.x * w0, hv.y * w1, hv.z * w2, hv.w * w3);

            if (qi < 7) { q += 4; ii = ii2; rc = rc2; hv = hv2; }
        }
        __syncthreads();
    }
}

extern "C" void kernel_launch(void* const* d_in, const int* in_sizes, int n_in,
                              void* d_out, int out_size)
{
    const float* x     = (const float*)d_in[0];
    const float* f_ij  = (const float*)d_in[1];
    const int*   idx_i = (const int*)d_in[2];
    const int*   idx_j = (const int*)d_in[3];
    const float* rcut  = (const float*)d_in[4];
    const float* W_in  = (const float*)d_in[5];
    const float* b_in  = (const float*)d_in[6];
    const float* W_f   = (const float*)d_in[7];
    const float* b_f   = (const float*)d_in[8];
    const float* W_out = (const float*)d_in[9];
    const float* b_out = (const float*)d_in[10];
    float* out = (float*)d_out;

    float* hptr = nullptr;
    float* aptr = nullptr;
    cudaGetSymbolAddress((void**)&hptr, g_h);
    cudaGetSymbolAddress((void**)&aptr, g_agg);

    const int ngrid = (N_ATOMS + 127) / 128;   // 313
    // GEMM #1 also zeroes agg (absorbs the standalone zero kernel)
    gemm_atoms<false, true><<<ngrid, 256>>>(x, W_in, b_in, hptr, aptr);
    pair_kernel<<<2048, 128>>>(f_ij, idx_i, idx_j, rcut, W_f, b_f, hptr, aptr);
    gemm_atoms<true, false><<<ngrid, 256>>>(aptr, W_out, b_out, out, aptr);
}

// round 16
// speedup vs baseline: 1.2696x; 1.1517x over previous
#include <cuda_runtime.h>
#include <cuda_bf16.h>
#include <cstdint>

#define N_ATOMS 40000
#define N_PAIRS 640000
#define DD 128
#define RR 20

// Scratch (allocation-free rule: static device globals)
__device__ float g_h[N_ATOMS * DD];    // 20.48 MB
__device__ float g_agg[N_ATOMS * DD];  // 20.48 MB

// Packed fp32x2 FMA (validated: GEMM runs at the FFMA2 rate wall)
#define FFMA2(acc, a, b) \
    asm("fma.rn.f32x2 %0, %1, %2, %0;" : "+l"(acc) : "l"(a), "l"(b))

__device__ __forceinline__ unsigned long long pack2(float x, float y) {
    unsigned long long d;
    asm("mov.b64 %0, {%1,%2};" : "=l"(d) : "f"(x), "f"(y));
    return d;
}
__device__ __forceinline__ void unpack2(unsigned long long d, float& x, float& y) {
    asm("mov.b64 {%0,%1}, %2;" : "=f"(x), "=f"(y) : "l"(d));
}
// No "memory" clobber: nothing reads agg intra-kernel; lets loads hoist.
__device__ __forceinline__ void red_add_v4(float* addr, float a, float b,
                                           float c, float d) {
    asm volatile("red.global.add.v4.f32 [%0], {%1, %2, %3, %4};"
                 :: "l"(addr), "f"(a), "f"(b), "f"(c), "f"(d));
}
__device__ __forceinline__ uint32_t smem_u32(const void* p) {
    uint32_t a;
    asm("{ .reg .u64 t; cvta.to.shared.u64 t, %1; cvt.u32.u64 %0, t; }"
        : "=r"(a) : "l"(p));
    return a;
}
#define CP_ASYNC16(saddr, gptr) \
    asm volatile("cp.async.ca.shared.global [%0], [%1], 16;" \
                 :: "r"(saddr), "l"(gptr) : "memory")
#define CP_COMMIT() asm volatile("cp.async.commit_group;" ::: "memory")
#define CP_WAIT0()  asm volatile("cp.async.wait_group 0;" ::: "memory")

// Branch-free shifted softplus: max(x,0) + log1p(e^-|x|) - ln2
__device__ __forceinline__ float sspf(float x) {
    float e = __expf(-fabsf(x));
    return fmaxf(x, 0.f) + (__logf(1.f + e) - 0.69314718055994531f);
}

// -----------------------------------------------------------------------------
// Tiled SGEMM — R12's measured-best (38.9us, at the FFMA2 rate wall).
// Double-buffered smem, one barrier per k-tile, register prefetch.
// ZERO variant also zeroes this block's slice of zbuf.
// -----------------------------------------------------------------------------
template <bool SSP, bool ZERO>
__global__ __launch_bounds__(256) void gemm_atoms(
    const float* __restrict__ A, const float* __restrict__ W,
    const float* __restrict__ bias, float* __restrict__ out,
    float* __restrict__ zbuf)
{
    __shared__ float As[2][16][68];
    __shared__ float Bs[2][16][132];

    const int tid  = threadIdx.x;
    const int tcol = tid & 31;
    const int trow = tid >> 5;
    const int a0   = blockIdx.x * 64;

    const int ar = tid >> 2, akg = (tid & 3) << 2;
    const int wc0 = tid >> 2,         wk0g = (tid & 3) << 2;
    const int wc1 = (tid + 256) >> 2, wk1g = ((tid + 256) & 3) << 2;

    if (ZERO) {
        float4* z = (float4*)(zbuf + (size_t)a0 * DD);
        const float4 z4 = make_float4(0.f, 0.f, 0.f, 0.f);
#pragma unroll
        for (int i = 0; i < 8; i++) z[tid + i * 256] = z4;
    }

    unsigned long long accp[4][4];
#pragma unroll
    for (int p = 0; p < 4; p++)
#pragma unroll
        for (int j = 0; j < 4; j++) accp[p][j] = 0ull;

    float4 va  = *(const float4*)&A[(size_t)(a0 + ar) * 128 + akg];
    float4 vw0 = *(const float4*)&W[(size_t)wc0 * 128 + wk0g];
    float4 vw1 = *(const float4*)&W[(size_t)wc1 * 128 + wk1g];

#pragma unroll
    for (int kt8 = 0; kt8 < 8; kt8++) {
        const int b = kt8 & 1;
        As[b][akg + 0][ar] = va.x; As[b][akg + 1][ar] = va.y;
        As[b][akg + 2][ar] = va.z; As[b][akg + 3][ar] = va.w;
        Bs[b][wk0g + 0][wc0] = vw0.x; Bs[b][wk0g + 1][wc0] = vw0.y;
        Bs[b][wk0g + 2][wc0] = vw0.z; Bs[b][wk0g + 3][wc0] = vw0.w;
        Bs[b][wk1g + 0][wc1] = vw1.x; Bs[b][wk1g + 1][wc1] = vw1.y;
        Bs[b][wk1g + 2][wc1] = vw1.z; Bs[b][wk1g + 3][wc1] = vw1.w;
        __syncthreads();

        if (kt8 < 7) {
            const int kt = (kt8 + 1) * 16;
            va  = *(const float4*)&A[(size_t)(a0 + ar) * 128 + kt + akg];
            vw0 = *(const float4*)&W[(size_t)wc0 * 128 + kt + wk0g];
            vw1 = *(const float4*)&W[(size_t)wc1 * 128 + kt + wk1g];
        }

#pragma unroll
        for (int k = 0; k < 16; k++) {
            float4 bv = *(const float4*)&Bs[b][k][tcol * 4];
            unsigned long long bb[4];
            bb[0] = pack2(bv.x, bv.x); bb[1] = pack2(bv.y, bv.y);
            bb[2] = pack2(bv.z, bv.z); bb[3] = pack2(bv.w, bv.w);
            const unsigned long long* ap =
                (const unsigned long long*)&As[b][k][trow * 8];
            unsigned long long a[4];
            a[0] = ap[0]; a[1] = ap[1]; a[2] = ap[2]; a[3] = ap[3];
#pragma unroll
            for (int p = 0; p < 4; p++)
#pragma unroll
                for (int j = 0; j < 4; j++) FFMA2(accp[p][j], a[p], bb[j]);
        }
    }

    float4 bia = *(const float4*)&bias[tcol * 4];
    float bb[4] = {bia.x, bia.y, bia.z, bia.w};
#pragma unroll
    for (int p = 0; p < 4; p++) {
        float lo[4], hi[4];
#pragma unroll
        for (int j = 0; j < 4; j++) {
            unpack2(accp[p][j], lo[j], hi[j]);
            lo[j] += bb[j]; hi[j] += bb[j];
            if (SSP) { lo[j] = sspf(lo[j]); hi[j] = sspf(hi[j]); }
        }
        size_t r0 = (size_t)(a0 + trow * 8 + 2 * p) * 128 + tcol * 4;
        *(float4*)&out[r0]       = make_float4(lo[0], lo[1], lo[2], lo[3]);
        *(float4*)&out[r0 + 128] = make_float4(hi[0], hi[1], hi[2], hi[3]);
    }
}

// -----------------------------------------------------------------------------
// Pair kernel v5: warp-per-pair, 4 ch/thread, TWO pairs interleaved per
// iteration (q, q+8) -> 8 independent FFMA2 chains + 2 gathers in flight.
// CHUNK=64, cp.async double-buffered. __launch_bounds__(128,3) caps regs
// at ~170 so occupancy stays 12 warps/SM while ILP doubles.
// -----------------------------------------------------------------------------
#define CHUNK 64

__global__ __launch_bounds__(128, 3) void pair_kernel(
    const float* __restrict__ f_ij, const int* __restrict__ idx_i,
    const int* __restrict__ idx_j, const float* __restrict__ rcut,
    const float* __restrict__ W_f, const float* __restrict__ b_f,
    const float* __restrict__ h, float* __restrict__ agg)
{
    __shared__ __align__(16) float sF[2][CHUNK * RR];  // 2 x 5KB
    __shared__ __align__(16) float sR[2][CHUNK];
    __shared__ __align__(16) int   sI[2][CHUNK];
    __shared__ __align__(16) int   sJ[2][CHUNK];

    const int tid  = threadIdx.x;
    const int lane = tid & 31;
    const int warp = tid >> 5;       // 0..3
    const int c0   = lane * 4;       // channels c0..c0+3

    // Persistent packed filter weights for 4 channels: 40 u64 regs.
    unsigned long long wk[4][10];
    float bf[4];
#pragma unroll
    for (int c = 0; c < 4; c++) {
        const float2* row = (const float2*)&W_f[(size_t)(c0 + c) * RR];
#pragma unroll
        for (int k = 0; k < 10; k++) {
            float2 v = __ldg(&row[k]);
            wk[c][k] = pack2(v.x, v.y);
        }
        bf[c] = __ldg(&b_f[c0 + c]);
    }

    const int nchunks = N_PAIRS / CHUNK;   // 10000

    auto stage = [&](int ch, int b) {
        const int base = ch * CHUNK;
        const char* fsrc = (const char*)&f_ij[(size_t)base * RR];
        uint32_t sf = smem_u32(&sF[b][0]);
        // f: 64*20 floats = 320 x 16B slots
        CP_ASYNC16(sf + tid * 16, fsrc + tid * 16);
        CP_ASYNC16(sf + (tid + 128) * 16, fsrc + (tid + 128) * 16);
        if (tid < 64) {
            CP_ASYNC16(sf + (tid + 256) * 16, fsrc + (tid + 256) * 16);
        } else if (tid < 80) {        // rcut: 16 x 16B
            int t = tid - 64;
            CP_ASYNC16(smem_u32(&sR[b][0]) + t * 16,
                       (const char*)&rcut[base] + t * 16);
        } else if (tid < 96) {        // idx_i
            int t = tid - 80;
            CP_ASYNC16(smem_u32(&sI[b][0]) + t * 16,
                       (const char*)&idx_i[base] + t * 16);
        } else if (tid < 112) {       // idx_j
            int t = tid - 96;
            CP_ASYNC16(smem_u32(&sJ[b][0]) + t * 16,
                       (const char*)&idx_j[base] + t * 16);
        }
        CP_COMMIT();
    };

    int ch = blockIdx.x;
    if (ch < nchunks) stage(ch, 0);

    int it = 0;
    for (; ch < nchunks; ch += gridDim.x, ++it) {
        const int buf = it & 1;
        CP_WAIT0();
        __syncthreads();
        const int nch = ch + gridDim.x;
        if (nch < nchunks) stage(nch, buf ^ 1);

        const int wbase = warp * 16;
#pragma unroll
        for (int qi = 0; qi < 8; qi++) {
            const int q0 = wbase + qi;
            const int q1 = q0 + 8;

            // Metadata + both gathers up front (L2 latency hidden under math)
            const int   ii0 = sI[buf][q0], ii1 = sI[buf][q1];
            const float rc0 = sR[buf][q0], rc1 = sR[buf][q1];
            const float4 hv0 = *(const float4*)&h[(size_t)sJ[buf][q0] * DD + c0];
            const float4 hv1 = *(const float4*)&h[(size_t)sJ[buf][q1] * DD + c0];

            // f rows for both pairs
            const float4* fp0 = (const float4*)&sF[buf][q0 * RR];
            const float4* fp1 = (const float4*)&sF[buf][q1 * RR];
            float4 u0 = fp0[0], u1 = fp0[1], u2 = fp0[2], u3 = fp0[3], u4 = fp0[4];
            float4 t0 = fp1[0], t1 = fp1[1], t2 = fp1[2], t3 = fp1[3], t4 = fp1[4];
            unsigned long long fa[10], fb[10];
            fa[0] = pack2(u0.x, u0.y); fa[1] = pack2(u0.z, u0.w);
            fa[2] = pack2(u1.x, u1.y); fa[3] = pack2(u1.z, u1.w);
            fa[4] = pack2(u2.x, u2.y); fa[5] = pack2(u2.z, u2.w);
            fa[6] = pack2(u3.x, u3.y); fa[7] = pack2(u3.z, u3.w);
            fa[8] = pack2(u4.x, u4.y); fa[9] = pack2(u4.z, u4.w);
            fb[0] = pack2(t0.x, t0.y); fb[1] = pack2(t0.z, t0.w);
            fb[2] = pack2(t1.x, t1.y); fb[3] = pack2(t1.z, t1.w);
            fb[4] = pack2(t2.x, t2.y); fb[5] = pack2(t2.z, t2.w);
            fb[6] = pack2(t3.x, t3.y); fb[7] = pack2(t3.z, t3.w);
            fb[8] = pack2(t4.x, t4.y); fb[9] = pack2(t4.z, t4.w);

            // 8 independent 10-deep FFMA2 chains (bias folded into init)
            unsigned long long a0 = pack2(bf[0], 0.f), b0 = a0;
            unsigned long long a1 = pack2(bf[1], 0.f), b1 = a1;
            unsigned long long a2 = pack2(bf[2], 0.f), b2 = a2;
            unsigned long long a3 = pack2(bf[3], 0.f), b3 = a3;
#pragma unroll
            for (int k = 0; k < 10; k++) {
                FFMA2(a0, fa[k], wk[0][k]);
                FFMA2(a1, fa[k], wk[1][k]);
                FFMA2(a2, fa[k], wk[2][k]);
                FFMA2(a3, fa[k], wk[3][k]);
                FFMA2(b0, fb[k], wk[0][k]);
                FFMA2(b1, fb[k], wk[1][k]);
                FFMA2(b2, fb[k], wk[2][k]);
                FFMA2(b3, fb[k], wk[3][k]);
            }
            float x0, y0, x1, y1, x2, y2, x3, y3;
            unpack2(a0, x0, y0); unpack2(a1, x1, y1);
            unpack2(a2, x2, y2); unpack2(a3, x3, y3);
            const float w00 = sspf(x0 + y0) * rc0;
            const float w01 = sspf(x1 + y1) * rc0;
            const float w02 = sspf(x2 + y2) * rc0;
            const float w03 = sspf(x3 + y3) * rc0;
            unpack2(b0, x0, y0); unpack2(b1, x1, y1);
            unpack2(b2, x2, y2); unpack2(b3, x3, y3);
            const float w10 = sspf(x0 + y0) * rc1;
            const float w11 = sspf(x1 + y1) * rc1;
            const float w12 = sspf(x2 + y2) * rc1;
            const float w13 = sspf(x3 + y3) * rc1;

            red_add_v4(&agg[(size_t)ii0 * DD + c0],
                       hv0.x * w00, hv0.y * w01, hv0.z * w02, hv0.w * w03);
            red_add_v4(&agg[(size_t)ii1 * DD + c0],
                       hv1.x * w10, hv1.y * w11, hv1.z * w12, hv1.w * w13);
        }
        __syncthreads();   // compute done before this buffer is restaged
    }
}

extern "C" void kernel_launch(void* const* d_in, const int* in_sizes, int n_in,
                              void* d_out, int out_size)
{
    const float* x     = (const float*)d_in[0];
    const float* f_ij  = (const float*)d_in[1];
    const int*   idx_i = (const int*)d_in[2];
    const int*   idx_j = (const int*)d_in[3];
    const float* rcut  = (const float*)d_in[4];
    const float* W_in  = (const float*)d_in[5];
    const float* b_in  = (const float*)d_in[6];
    const float* W_f   = (const float*)d_in[7];
    const float* b_f   = (const float*)d_in[8];
    const float* W_out = (const float*)d_in[9];
    const float* b_out = (const float*)d_in[10];
    float* out = (float*)d_out;

    float* hptr = nullptr;
    float* aptr = nullptr;
    cudaGetSymbolAddress((void**)&hptr, g_h);
    cudaGetSymbolAddress((void**)&aptr, g_agg);

    // GEMM #1 also zeroes agg (absorbs the standalone zero kernel)
    gemm_atoms<false, true><<<N_ATOMS / 64, 256>>>(x, W_in, b_in, hptr, aptr);
    pair_kernel<<<1024, 128>>>(f_ij, idx_i, idx_j, rcut, W_f, b_f, hptr, aptr);
    gemm_atoms<true, false><<<N_ATOMS / 64, 256>>>(aptr, W_out, b_out, out, aptr);
}